// round 1
// baseline (speedup 1.0000x reference)
#include <cuda_runtime.h>

#define BATCH 4
#define CDIM  256
#define NDIM  4096
#define OC3   768

// Scratch (static device globals — no allocations allowed in kernel_launch)
__device__ float g_qkv[(size_t)BATCH * OC3 * NDIM];            // 50 MB  [b][o][n], o: 0..255 Q, 256..511 K, 512..767 V
__device__ float g_scores[(size_t)BATCH * NDIM * NDIM];        // 268 MB [b][i][j]
__device__ float g_attn[(size_t)BATCH * CDIM * NDIM];          // 17 MB  [b][c][i]

// ---------------------------------------------------------------------------
// Kernel A: qkv[b][o][n] = sum_c W[o][c] * x[b][c][n] + bias[o]
// 64x64 output tile, K-chunk 64. block (16,16), 4x4 per thread.
// ---------------------------------------------------------------------------
__global__ void qkv_gemm(const float* __restrict__ x,
                         const float* __restrict__ w,
                         const float* __restrict__ bias) {
    __shared__ float Ws[64][65];   // [o][c]
    __shared__ float Xs[64][65];   // [c][n]
    const int b  = blockIdx.z;
    const int o0 = blockIdx.y * 64;
    const int n0 = blockIdx.x * 64;
    const int tx = threadIdx.x, ty = threadIdx.y;
    const int tid = ty * 16 + tx;
    const float* xb = x + (size_t)b * CDIM * NDIM;

    float acc[4][4] = {};
    for (int c0 = 0; c0 < CDIM; c0 += 64) {
        #pragma unroll
        for (int e = tid; e < 64 * 64; e += 256) {
            int r = e >> 6, cc = e & 63;
            Ws[r][cc] = w[(o0 + r) * CDIM + c0 + cc];
            Xs[r][cc] = xb[(size_t)(c0 + r) * NDIM + n0 + cc];
        }
        __syncthreads();
        #pragma unroll
        for (int kk = 0; kk < 64; kk++) {
            float a[4], bb[4];
            #pragma unroll
            for (int i = 0; i < 4; i++) a[i]  = Ws[ty * 4 + i][kk];
            #pragma unroll
            for (int j = 0; j < 4; j++) bb[j] = Xs[kk][tx * 4 + j];
            #pragma unroll
            for (int i = 0; i < 4; i++)
                #pragma unroll
                for (int j = 0; j < 4; j++)
                    acc[i][j] += a[i] * bb[j];
        }
        __syncthreads();
    }
    #pragma unroll
    for (int i = 0; i < 4; i++) {
        const int o = o0 + ty * 4 + i;
        const float bv = bias[o];
        #pragma unroll
        for (int j = 0; j < 4; j++)
            g_qkv[((size_t)b * OC3 + o) * NDIM + n0 + tx * 4 + j] = acc[i][j] + bv;
    }
}

// ---------------------------------------------------------------------------
// Kernel B: scores[b][i][j] = (1/16) * sum_c Q[b][c][i] * K[b][c][j]
// Both operands reduction-major (stride NDIM over c) -> coalesced tile loads.
// ---------------------------------------------------------------------------
__global__ void scores_gemm() {
    __shared__ float Qs[64][65];   // [c][i]
    __shared__ float Ks[64][65];   // [c][j]
    const int b  = blockIdx.z;
    const int i0 = blockIdx.y * 64;
    const int j0 = blockIdx.x * 64;
    const int tx = threadIdx.x, ty = threadIdx.y;
    const int tid = ty * 16 + tx;
    const float* Q = g_qkv + (size_t)b * OC3 * NDIM;           // o in [0,256)
    const float* K = Q + (size_t)CDIM * NDIM;                  // o in [256,512)

    float acc[4][4] = {};
    for (int c0 = 0; c0 < CDIM; c0 += 64) {
        #pragma unroll
        for (int e = tid; e < 64 * 64; e += 256) {
            int r = e >> 6, cc = e & 63;
            Qs[r][cc] = Q[(size_t)(c0 + r) * NDIM + i0 + cc];
            Ks[r][cc] = K[(size_t)(c0 + r) * NDIM + j0 + cc];
        }
        __syncthreads();
        #pragma unroll
        for (int kk = 0; kk < 64; kk++) {
            float a[4], bb[4];
            #pragma unroll
            for (int i = 0; i < 4; i++) a[i]  = Qs[kk][ty * 4 + i];
            #pragma unroll
            for (int j = 0; j < 4; j++) bb[j] = Ks[kk][tx * 4 + j];
            #pragma unroll
            for (int i = 0; i < 4; i++)
                #pragma unroll
                for (int j = 0; j < 4; j++)
                    acc[i][j] += a[i] * bb[j];
        }
        __syncthreads();
    }
    const float scale = 0.0625f;   // 1/sqrt(256)
    #pragma unroll
    for (int i = 0; i < 4; i++)
        #pragma unroll
        for (int j = 0; j < 4; j++)
            g_scores[((size_t)b * NDIM + i0 + ty * 4 + i) * NDIM + j0 + tx * 4 + j] =
                acc[i][j] * scale;
}

// ---------------------------------------------------------------------------
// Kernel C: row softmax over j (N=4096). One block of 256 threads per row.
// ---------------------------------------------------------------------------
__global__ void softmax_rows() {
    __shared__ float red[256];
    const size_t row = blockIdx.x;
    float* s = g_scores + row * NDIM;
    const int t = threadIdx.x;

    float m = -1e30f;
    for (int j = t; j < NDIM; j += 256) m = fmaxf(m, s[j]);
    red[t] = m;
    __syncthreads();
    for (int st = 128; st > 0; st >>= 1) {
        if (t < st) red[t] = fmaxf(red[t], red[t + st]);
        __syncthreads();
    }
    m = red[0];
    __syncthreads();

    float sum = 0.f;
    for (int j = t; j < NDIM; j += 256) {
        float e = __expf(s[j] - m);
        s[j] = e;
        sum += e;
    }
    red[t] = sum;
    __syncthreads();
    for (int st = 128; st > 0; st >>= 1) {
        if (t < st) red[t] += red[t + st];
        __syncthreads();
    }
    const float inv = 1.0f / red[0];
    for (int j = t; j < NDIM; j += 256) s[j] *= inv;
}

// ---------------------------------------------------------------------------
// Kernel D: attn_out[b][c][i] = sum_j attn[b][i][j] * V[b][c][j]
// Reduction over j (contiguous in both operands) -> GEMM-NT.
// ---------------------------------------------------------------------------
__global__ void attnv_gemm() {
    __shared__ float Vs[64][65];   // [c][j]
    __shared__ float Ss[64][65];   // [i][j]
    const int b  = blockIdx.z;
    const int c0 = blockIdx.y * 64;
    const int i0 = blockIdx.x * 64;
    const int tx = threadIdx.x, ty = threadIdx.y;
    const int tid = ty * 16 + tx;
    const float* V = g_qkv + ((size_t)b * OC3 + 2 * CDIM) * NDIM;  // o in [512,768)
    const float* S = g_scores + (size_t)b * NDIM * NDIM;

    float acc[4][4] = {};
    for (int j0 = 0; j0 < NDIM; j0 += 64) {
        #pragma unroll
        for (int e = tid; e < 64 * 64; e += 256) {
            int r = e >> 6, cc = e & 63;
            Vs[r][cc] = V[(size_t)(c0 + r) * NDIM + j0 + cc];
            Ss[r][cc] = S[(size_t)(i0 + r) * NDIM + j0 + cc];
        }
        __syncthreads();
        #pragma unroll
        for (int kk = 0; kk < 64; kk++) {
            float a[4], bb[4];
            #pragma unroll
            for (int ci = 0; ci < 4; ci++) a[ci]  = Vs[ty * 4 + ci][kk];
            #pragma unroll
            for (int ii = 0; ii < 4; ii++) bb[ii] = Ss[tx * 4 + ii][kk];
            #pragma unroll
            for (int ci = 0; ci < 4; ci++)
                #pragma unroll
                for (int ii = 0; ii < 4; ii++)
                    acc[ci][ii] += a[ci] * bb[ii];
        }
        __syncthreads();
    }
    #pragma unroll
    for (int ci = 0; ci < 4; ci++)
        #pragma unroll
        for (int ii = 0; ii < 4; ii++)
            g_attn[((size_t)b * CDIM + c0 + ty * 4 + ci) * NDIM + i0 + tx * 4 + ii] =
                acc[ci][ii];
}

// ---------------------------------------------------------------------------
// Kernel E: y[b][o][n] = x[b][o][n] + bias[o] + sum_c Wp[o][c] * attn_out[b][c][n]
// ---------------------------------------------------------------------------
__global__ void proj_gemm(const float* __restrict__ x,
                          const float* __restrict__ w,
                          const float* __restrict__ bias,
                          float* __restrict__ out) {
    __shared__ float Ws[64][65];   // [o][c]
    __shared__ float As[64][65];   // [c][n]
    const int b  = blockIdx.z;
    const int o0 = blockIdx.y * 64;
    const int n0 = blockIdx.x * 64;
    const int tx = threadIdx.x, ty = threadIdx.y;
    const int tid = ty * 16 + tx;

    float acc[4][4] = {};
    for (int c0 = 0; c0 < CDIM; c0 += 64) {
        #pragma unroll
        for (int e = tid; e < 64 * 64; e += 256) {
            int r = e >> 6, cc = e & 63;
            Ws[r][cc] = w[(o0 + r) * CDIM + c0 + cc];
            As[r][cc] = g_attn[((size_t)b * CDIM + c0 + r) * NDIM + n0 + cc];
        }
        __syncthreads();
        #pragma unroll
        for (int kk = 0; kk < 64; kk++) {
            float a[4], bb[4];
            #pragma unroll
            for (int i = 0; i < 4; i++) a[i]  = Ws[ty * 4 + i][kk];
            #pragma unroll
            for (int j = 0; j < 4; j++) bb[j] = As[kk][tx * 4 + j];
            #pragma unroll
            for (int i = 0; i < 4; i++)
                #pragma unroll
                for (int j = 0; j < 4; j++)
                    acc[i][j] += a[i] * bb[j];
        }
        __syncthreads();
    }
    #pragma unroll
    for (int i = 0; i < 4; i++) {
        const int o = o0 + ty * 4 + i;
        const float bv = bias[o];
        #pragma unroll
        for (int j = 0; j < 4; j++) {
            const size_t idx = ((size_t)b * CDIM + o) * NDIM + n0 + tx * 4 + j;
            out[idx] = x[idx] + bv + acc[i][j];
        }
    }
}

// ---------------------------------------------------------------------------
extern "C" void kernel_launch(void* const* d_in, const int* in_sizes, int n_in,
                              void* d_out, int out_size) {
    const float* x      = (const float*)d_in[0];
    const float* w_qkv  = (const float*)d_in[1];
    const float* b_qkv  = (const float*)d_in[2];
    const float* w_proj = (const float*)d_in[3];
    const float* b_proj = (const float*)d_in[4];
    float* out = (float*)d_out;

    dim3 blk(16, 16);
    qkv_gemm   <<<dim3(NDIM / 64, OC3 / 64, BATCH), blk>>>(x, w_qkv, b_qkv);
    scores_gemm<<<dim3(NDIM / 64, NDIM / 64, BATCH), blk>>>();
    softmax_rows<<<BATCH * NDIM, 256>>>();
    attnv_gemm <<<dim3(NDIM / 64, CDIM / 64, BATCH), blk>>>();
    proj_gemm  <<<dim3(NDIM / 64, CDIM / 64, BATCH), blk>>>(x, w_proj, b_proj, out);
}

// round 2
// speedup vs baseline: 6.3389x; 6.3389x over previous
#include <cuda_runtime.h>

#define BATCH 4
#define CDIM  256
#define NDIM  4096
#define OC3   768

// Scratch (static device globals — no allocations allowed)
__device__ float g_qkv[(size_t)BATCH * OC3 * NDIM];        // [b][o][n] o:0..255 Q, 256..511 K, 512..767 V
__device__ float g_scores[(size_t)BATCH * NDIM * NDIM];    // [b][i][j]
__device__ float g_attn[(size_t)BATCH * CDIM * NDIM];      // [b][c][i]

__device__ __forceinline__ unsigned f2tf(float x) {
    unsigned u;
    asm("cvt.rna.tf32.f32 %0, %1;" : "=r"(u) : "f"(x));
    return u;
}

__device__ __forceinline__ void mma8(float c[4], const unsigned a[4], const unsigned b[2]) {
    asm volatile(
        "mma.sync.aligned.m16n8k8.row.col.f32.tf32.tf32.f32 "
        "{%0,%1,%2,%3}, {%4,%5,%6,%7}, {%8,%9}, {%0,%1,%2,%3};"
        : "+f"(c[0]), "+f"(c[1]), "+f"(c[2]), "+f"(c[3])
        : "r"(a[0]), "r"(a[1]), "r"(a[2]), "r"(a[3]), "r"(b[0]), "r"(b[1]));
}

// ---------------------------------------------------------------------------
// Generic tf32 tensor-core GEMM: C[m][n] = epi( sum_k A(m,k) * B(k,n) )
// Block tile 128x128, K-chunk 32. 8 warps = 4(M) x 2(N), warp tile 32x64.
// AKC: A is k-contiguous in gmem (ak==1) -> smem [m][k] stride 36
//      else A is m-contiguous (am==1)   -> smem [k][m] stride 136
// BKC: B is k-contiguous (bk==1)        -> smem [n][k] stride 36
//      else B is n-contiguous (bn==1)   -> smem [k][n] stride 136
// EPI: 0 plain | 1 *scale | 2 +bias[m] | 3 +bias[m]+X (residual)
// ---------------------------------------------------------------------------
template<bool AKC, bool BKC, int EPI>
__global__ void __launch_bounds__(256, 2) gemm_tf32(
    const float* __restrict__ A, long am, long ak, long aB,
    const float* __restrict__ B, long bk, long bn, long bB,
    float* __restrict__ C, long cB,
    int KT, float scale,
    const float* __restrict__ bias,
    const float* __restrict__ X, long xB)
{
    __shared__ unsigned As[AKC ? 128 * 36 : 32 * 136];
    __shared__ unsigned Bs[BKC ? 128 * 36 : 32 * 136];

    const int bz = blockIdx.z;
    const int M0 = blockIdx.y * 128;
    const int N0 = blockIdx.x * 128;
    A += (size_t)bz * aB;
    B += (size_t)bz * bB;
    C += (size_t)bz * cB;
    if (EPI == 3) X += (size_t)bz * xB;

    const int tid  = threadIdx.x;
    const int wid  = tid >> 5;
    const int lane = tid & 31;
    const int g    = lane >> 2;       // group id 0..7
    const int tg   = lane & 3;        // thread-in-group 0..3
    const int wm   = (wid & 3) * 32;  // warp M offset in block tile
    const int wn   = (wid >> 2) * 64; // warp N offset

    float c[2][8][4];
    #pragma unroll
    for (int mt = 0; mt < 2; mt++)
        #pragma unroll
        for (int nt = 0; nt < 8; nt++)
            #pragma unroll
            for (int e = 0; e < 4; e++) c[mt][nt][e] = 0.f;

    for (int kk0 = 0; kk0 < KT; kk0 += 32) {
        // ---- fill A tile ----
        if (AKC) {
            #pragma unroll
            for (int e = tid; e < 128 * 32; e += 256) {
                int m = e >> 5, k = e & 31;
                As[m * 36 + k] = f2tf(A[(size_t)(M0 + m) * am + kk0 + k]);
            }
        } else {
            #pragma unroll
            for (int e = tid; e < 32 * 32; e += 256) {
                int k = e >> 5, m4 = e & 31;
                float4 v = *(const float4*)(A + (size_t)(kk0 + k) * ak + M0 + 4 * m4);
                As[k * 136 + 4 * m4 + 0] = f2tf(v.x);
                As[k * 136 + 4 * m4 + 1] = f2tf(v.y);
                As[k * 136 + 4 * m4 + 2] = f2tf(v.z);
                As[k * 136 + 4 * m4 + 3] = f2tf(v.w);
            }
        }
        // ---- fill B tile ----
        if (BKC) {
            #pragma unroll
            for (int e = tid; e < 128 * 32; e += 256) {
                int n = e >> 5, k = e & 31;
                Bs[n * 36 + k] = f2tf(B[(size_t)(N0 + n) * bn + kk0 + k]);
            }
        } else {
            #pragma unroll
            for (int e = tid; e < 32 * 32; e += 256) {
                int k = e >> 5, n4 = e & 31;
                float4 v = *(const float4*)(B + (size_t)(kk0 + k) * bk + N0 + 4 * n4);
                Bs[k * 136 + 4 * n4 + 0] = f2tf(v.x);
                Bs[k * 136 + 4 * n4 + 1] = f2tf(v.y);
                Bs[k * 136 + 4 * n4 + 2] = f2tf(v.z);
                Bs[k * 136 + 4 * n4 + 3] = f2tf(v.w);
            }
        }
        __syncthreads();

        // ---- 4 k-steps of 8 ----
        #pragma unroll
        for (int ks = 0; ks < 4; ks++) {
            const int k0 = ks * 8;
            unsigned a[2][4], b[8][2];
            #pragma unroll
            for (int mt = 0; mt < 2; mt++) {
                const int mrow = wm + mt * 16 + g;
                if (AKC) {
                    a[mt][0] = As[(mrow)     * 36 + k0 + tg];
                    a[mt][1] = As[(mrow + 8) * 36 + k0 + tg];
                    a[mt][2] = As[(mrow)     * 36 + k0 + tg + 4];
                    a[mt][3] = As[(mrow + 8) * 36 + k0 + tg + 4];
                } else {
                    a[mt][0] = As[(k0 + tg)     * 136 + mrow];
                    a[mt][1] = As[(k0 + tg)     * 136 + mrow + 8];
                    a[mt][2] = As[(k0 + tg + 4) * 136 + mrow];
                    a[mt][3] = As[(k0 + tg + 4) * 136 + mrow + 8];
                }
            }
            #pragma unroll
            for (int nt = 0; nt < 8; nt++) {
                const int ncol = wn + nt * 8 + g;
                if (BKC) {
                    b[nt][0] = Bs[ncol * 36 + k0 + tg];
                    b[nt][1] = Bs[ncol * 36 + k0 + tg + 4];
                } else {
                    b[nt][0] = Bs[(k0 + tg)     * 136 + ncol];
                    b[nt][1] = Bs[(k0 + tg + 4) * 136 + ncol];
                }
            }
            #pragma unroll
            for (int nt = 0; nt < 8; nt++)
                #pragma unroll
                for (int mt = 0; mt < 2; mt++)
                    mma8(c[mt][nt], a[mt], b[nt]);
        }
        __syncthreads();
    }

    // ---- epilogue ----
    #pragma unroll
    for (int mt = 0; mt < 2; mt++) {
        const int r0 = M0 + wm + mt * 16 + g;
        const int r1 = r0 + 8;
        float bv0 = 0.f, bv1 = 0.f;
        if (EPI >= 2) { bv0 = bias[r0]; bv1 = bias[r1]; }
        #pragma unroll
        for (int nt = 0; nt < 8; nt++) {
            const int col = N0 + wn + nt * 8 + 2 * tg;
            float v00 = c[mt][nt][0], v01 = c[mt][nt][1];
            float v10 = c[mt][nt][2], v11 = c[mt][nt][3];
            if (EPI == 1) { v00 *= scale; v01 *= scale; v10 *= scale; v11 *= scale; }
            if (EPI >= 2) { v00 += bv0; v01 += bv0; v10 += bv1; v11 += bv1; }
            if (EPI == 3) {
                const float2 x0 = *(const float2*)(X + (size_t)r0 * NDIM + col);
                const float2 x1 = *(const float2*)(X + (size_t)r1 * NDIM + col);
                v00 += x0.x; v01 += x0.y; v10 += x1.x; v11 += x1.y;
            }
            *(float2*)(C + (size_t)r0 * NDIM + col) = make_float2(v00, v01);
            *(float2*)(C + (size_t)r1 * NDIM + col) = make_float2(v10, v11);
        }
    }
}

// ---------------------------------------------------------------------------
// Row softmax over j (N=4096). One block of 256 threads per row.
// ---------------------------------------------------------------------------
__global__ void softmax_rows() {
    __shared__ float red[256];
    const size_t row = blockIdx.x;
    float* s = g_scores + row * NDIM;
    const int t = threadIdx.x;

    float m = -1e30f;
    for (int j = t; j < NDIM; j += 256) m = fmaxf(m, s[j]);
    red[t] = m;
    __syncthreads();
    for (int st = 128; st > 0; st >>= 1) {
        if (t < st) red[t] = fmaxf(red[t], red[t + st]);
        __syncthreads();
    }
    m = red[0];
    __syncthreads();

    float sum = 0.f;
    for (int j = t; j < NDIM; j += 256) {
        float e = __expf(s[j] - m);
        s[j] = e;
        sum += e;
    }
    red[t] = sum;
    __syncthreads();
    for (int st = 128; st > 0; st >>= 1) {
        if (t < st) red[t] += red[t + st];
        __syncthreads();
    }
    const float inv = 1.0f / red[0];
    for (int j = t; j < NDIM; j += 256) s[j] *= inv;
}

// ---------------------------------------------------------------------------
extern "C" void kernel_launch(void* const* d_in, const int* in_sizes, int n_in,
                              void* d_out, int out_size) {
    const float* x      = (const float*)d_in[0];
    const float* w_qkv  = (const float*)d_in[1];
    const float* b_qkv  = (const float*)d_in[2];
    const float* w_proj = (const float*)d_in[3];
    const float* b_proj = (const float*)d_in[4];
    float* out = (float*)d_out;

    float* qkv    = nullptr;
    float* scores = nullptr;
    float* attn   = nullptr;
    cudaGetSymbolAddress((void**)&qkv,    g_qkv);
    cudaGetSymbolAddress((void**)&scores, g_scores);
    cudaGetSymbolAddress((void**)&attn,   g_attn);

    // 1) QKV: C[o][n] = W[o][c] * X[c][n] + b   (A k-contig, B n-contig)
    gemm_tf32<true, false, 2><<<dim3(NDIM / 128, OC3 / 128, BATCH), 256>>>(
        w_qkv, CDIM, 1, 0,
        x, NDIM, 1, (long)CDIM * NDIM,
        qkv, (long)OC3 * NDIM,
        CDIM, 1.f, b_qkv, nullptr, 0);

    // 2) scores[i][j] = (1/16) * Q[c][i]^T K[c][j]   (A m-contig, B n-contig)
    gemm_tf32<false, false, 1><<<dim3(NDIM / 128, NDIM / 128, BATCH), 256>>>(
        qkv, 1, NDIM, (long)OC3 * NDIM,
        qkv + (size_t)CDIM * NDIM, NDIM, 1, (long)OC3 * NDIM,
        scores, (long)NDIM * NDIM,
        CDIM, 0.0625f, nullptr, nullptr, 0);

    // 3) softmax over j
    softmax_rows<<<BATCH * NDIM, 256>>>();

    // 4) attn_out[c][i] = V[c][j] * S[i][j]^T   (A k-contig, B k-contig)
    gemm_tf32<true, true, 0><<<dim3(NDIM / 128, CDIM / 128, BATCH), 256>>>(
        qkv + (size_t)2 * CDIM * NDIM, NDIM, 1, (long)OC3 * NDIM,
        scores, 1, NDIM, (long)NDIM * NDIM,
        attn, (long)CDIM * NDIM,
        NDIM, 1.f, nullptr, nullptr, 0);

    // 5) out[o][n] = x + b + Wp[o][c] * attn[c][n]   (A k-contig, B n-contig)
    gemm_tf32<true, false, 3><<<dim3(NDIM / 128, CDIM / 128, BATCH), 256>>>(
        w_proj, CDIM, 1, 0,
        attn, NDIM, 1, (long)CDIM * NDIM,
        out, (long)CDIM * NDIM,
        CDIM, 1.f, b_proj, x, (long)CDIM * NDIM);
}